// round 14
// baseline (speedup 1.0000x reference)
#include <cuda_runtime.h>
#include <cuda_bf16.h>
#include <cstdint>
#include <cstddef>

// ---------------------------------------------------------------------------
// Scratch (__device__ globals; no cudaMalloc allowed)
// ---------------------------------------------------------------------------
__device__ float g_c[64];
__device__ __align__(16) __nv_bfloat16 g_Mhi[64 * 1024];
__device__ __align__(16) __nv_bfloat16 g_Mlo[64 * 1024];

// ---------------------------------------------------------------------------
// Kernel A (fused): blocks [0,8192): M[k,d] = V[k,d] + sum_e W[k,d,e]*x2[e]
//                   blocks [8192,8256): c[k] = b[k] + V2[k]·x2
// One warp per (k,d) pair; streams 256 MB of W once (HBM-bound, ~82% DRAM).
// ---------------------------------------------------------------------------
__global__ __launch_bounds__(256) void wx2_kernel(const float* __restrict__ W,
                                                  const float* __restrict__ V,
                                                  const float* __restrict__ x2,
                                                  const float* __restrict__ b) {
    if (blockIdx.x >= 8192) {
        int k = blockIdx.x - 8192;
        if (threadIdx.x < 32) {
            int lane = threadIdx.x;
            const float4* v = reinterpret_cast<const float4*>(V + (size_t)k * 2048 + 1024);
            const float4* xx = reinterpret_cast<const float4*>(x2);
            float s = 0.0f;
#pragma unroll
            for (int i = 0; i < 8; i++) {
                float4 a = v[lane + i * 32];
                float4 c = xx[lane + i * 32];
                s += a.x * c.x + a.y * c.y + a.z * c.z + a.w * c.w;
            }
#pragma unroll
            for (int o = 16; o; o >>= 1) s += __shfl_xor_sync(0xFFFFFFFFu, s, o);
            if (lane == 0) g_c[k] = s + b[k];
        }
        return;
    }

    __shared__ float sx2[1024];
    {
        const float4* src = reinterpret_cast<const float4*>(x2);
        float4* dst = reinterpret_cast<float4*>(sx2);
        dst[threadIdx.x] = src[threadIdx.x];
    }
    __syncthreads();

    int pair = blockIdx.x * 8 + (threadIdx.x >> 5);
    int lane = threadIdx.x & 31;
    int k = pair >> 10;
    int d = pair & 1023;

    const float4* w = reinterpret_cast<const float4*>(W + (size_t)pair * 1024);
    const float4* xx = reinterpret_cast<const float4*>(sx2);

    float s = 0.0f;
#pragma unroll
    for (int i = 0; i < 8; i++) {
        float4 wv = __ldcs(&w[lane + i * 32]);   // streaming: W touched exactly once
        float4 xv = xx[lane + i * 32];
        s += wv.x * xv.x + wv.y * xv.y + wv.z * xv.z + wv.w * xv.w;
    }
#pragma unroll
    for (int o = 16; o; o >>= 1) s += __shfl_xor_sync(0xFFFFFFFFu, s, o);

    if (lane == 0) {
        float m = s + V[(size_t)k * 2048 + d];
        __nv_bfloat16 hi = __float2bfloat16_rn(m);
        __nv_bfloat16 lo = __float2bfloat16_rn(m - __bfloat162float(hi));
        g_Mhi[pair] = hi;
        g_Mlo[pair] = lo;
    }
}

// ---------------------------------------------------------------------------
// Kernel B: split-bf16 HMMA GEMM + fused relu/U epilogue.
// out[n] = sum_k relu((x1 @ M^T)[n,k] + c[k]) * U[k]
// Grid 128 CTAs (BM=64), 512 thr (16 warps as 4x4). Decoupled A pipeline:
// x1 LDGs issued TWO chunks ahead (2 register sets); sts_a at top of iter
// from registers loaded a full iteration earlier -> no exposed LDG wait.
// ---------------------------------------------------------------------------
#define CHUNK     128
#define LDA       136
#define A_HI      0
#define A_LO      17408
#define B_HI      34816
#define B_LO      52224
#define STAGE_BYTES 69632
#define RED_OFF   (2 * STAGE_BYTES)      // 139264
#define SMEM_TOTAL (RED_OFF + 1024)      // 140288

__device__ __forceinline__ uint32_t smem_u32(const void* p) {
    return (uint32_t)__cvta_generic_to_shared(p);
}

#define CP_ASYNC16(dst_u32, src_ptr) \
    asm volatile("cp.async.cg.shared.global [%0], [%1], 16;" :: "r"(dst_u32), "l"(src_ptr))
#define CP_COMMIT() asm volatile("cp.async.commit_group;" ::: "memory")
#define CP_WAIT0()  asm volatile("cp.async.wait_group 0;" ::: "memory")

#define LDSM4(r0, r1, r2, r3, addr) \
    asm volatile("ldmatrix.sync.aligned.m8n8.x4.shared.b16 {%0,%1,%2,%3}, [%4];" \
                 : "=r"(r0), "=r"(r1), "=r"(r2), "=r"(r3) : "r"(addr))

__device__ __forceinline__ uint32_t pack_bf16x2(__nv_bfloat16 a, __nv_bfloat16 b) {
    __nv_bfloat162 t; t.x = a; t.y = b;
    return *reinterpret_cast<uint32_t*>(&t);
}

__device__ __forceinline__ void split_pair(float f0, float f1, uint32_t& h, uint32_t& l) {
    __nv_bfloat16 h0 = __float2bfloat16_rn(f0);
    __nv_bfloat16 h1 = __float2bfloat16_rn(f1);
    h = pack_bf16x2(h0, h1);
    l = pack_bf16x2(__float2bfloat16_rn(f0 - __bfloat162float(h0)),
                    __float2bfloat16_rn(f1 - __bfloat162float(h1)));
}

__device__ __forceinline__ void mma16816(float d[4], const uint32_t a[4],
                                         uint32_t b0, uint32_t b1) {
    asm volatile(
        "mma.sync.aligned.m16n8k16.row.col.f32.bf16.bf16.f32 "
        "{%0,%1,%2,%3}, {%4,%5,%6,%7}, {%8,%9}, {%0,%1,%2,%3};"
        : "+f"(d[0]), "+f"(d[1]), "+f"(d[2]), "+f"(d[3])
        : "r"(a[0]), "r"(a[1]), "r"(a[2]), "r"(a[3]), "r"(b0), "r"(b1));
}

// A chunk: 64 rows x 128 fp32 = 2048 float4; 4 per thread (512 thr)
__device__ __forceinline__ void ldg_a(const float* __restrict__ x1, int row0, int ch,
                                      int tid, float4 pa[4]) {
#pragma unroll
    for (int t = 0; t < 4; t++) {
        int g = tid + t * 512;              // 0..2047
        int r = g >> 5;                     // row 0..63
        int c4 = (g & 31) * 4;              // col 0..124
        pa[t] = *reinterpret_cast<const float4*>(x1 + (size_t)(row0 + r) * 1024 + ch * CHUNK + c4);
    }
}

// B chunk via cp.async: hi + lo, 64 rows x 16 x 16B units each
__device__ __forceinline__ void cpasync_b(char* stage, int ch, int tid) {
    uint32_t sh = smem_u32(stage + B_HI);
    uint32_t sl = smem_u32(stage + B_LO);
#pragma unroll
    for (int t = 0; t < 2; t++) {
        int g = tid + t * 512;              // 0..1023
        int n = g >> 4;                     // k_out 0..63
        int u = g & 15;                     // 16B unit 0..15
        uint32_t doff = (uint32_t)(n * (LDA * 2) + u * 16);
        const __nv_bfloat16* srch = g_Mhi + (size_t)n * 1024 + ch * CHUNK + u * 8;
        const __nv_bfloat16* srcl = g_Mlo + (size_t)n * 1024 + ch * CHUNK + u * 8;
        CP_ASYNC16(sh + doff, srch);
        CP_ASYNC16(sl + doff, srcl);
    }
}

__device__ __forceinline__ void sts_a(char* stage, int tid, const float4 pa[4]) {
#pragma unroll
    for (int t = 0; t < 4; t++) {
        int g = tid + t * 512;
        int r = g >> 5;
        int c4 = (g & 31) * 4;
        uint32_t h0, l0, h1, l1;
        split_pair(pa[t].x, pa[t].y, h0, l0);
        split_pair(pa[t].z, pa[t].w, h1, l1);
        int off = (r * LDA + c4) * 2;
        *reinterpret_cast<uint2*>(stage + A_HI + off) = make_uint2(h0, h1);
        *reinterpret_cast<uint2*>(stage + A_LO + off) = make_uint2(l0, l1);
    }
}

// Warp tile 16m x 16n; 4 LDSM.x4 + 6 MMA per ks; 2 accumulator chains.
__device__ __forceinline__ void compute_chunk(uint32_t st, int m0, int nb,
                                              int lane, float d[2][4]) {
    int arow = m0 + (lane & 15);
    int acol = (lane >> 4) << 3;                 // 0 or 8
    int nrow = (lane & 7) + ((lane & 16) >> 1);  // 0..15
    int bcol = lane & 8;                         // 0 or 8
    uint32_t ah = st + A_HI + (uint32_t)(arow * LDA + acol) * 2;
    uint32_t al = st + A_LO + (uint32_t)(arow * LDA + acol) * 2;
    uint32_t ph = st + B_HI + (uint32_t)((nb + nrow) * LDA + bcol) * 2;
    uint32_t pl = st + B_LO + (uint32_t)((nb + nrow) * LDA + bcol) * 2;

#pragma unroll
    for (int ks = 0; ks < CHUNK / 16; ks++) {
        uint32_t koff = (uint32_t)ks * 32;
        uint32_t A[4], C[4];
        uint32_t p0, p1, p2, p3;
        uint32_t r0, r1, r2, r3;
        LDSM4(A[0], A[1], A[2], A[3], ah + koff);
        LDSM4(C[0], C[1], C[2], C[3], al + koff);
        LDSM4(p0, p1, p2, p3, ph + koff);
        LDSM4(r0, r1, r2, r3, pl + koff);
        mma16816(d[0], A, p0, p1);
        mma16816(d[1], A, p2, p3);
        mma16816(d[0], A, r0, r1);
        mma16816(d[1], A, r2, r3);
        mma16816(d[0], C, p0, p1);
        mma16816(d[1], C, p2, p3);
    }
}

__global__ __launch_bounds__(512, 1) void gemm_mma(const float* __restrict__ x1,
                                                   const float* __restrict__ U,
                                                   float* __restrict__ out) {
    extern __shared__ char smem[];
    int tid = threadIdx.x, lane = tid & 31, wid = tid >> 5;
    int wr = wid & 3, wc = wid >> 2;             // 4x4 warp grid
    int m0 = wr * 16, nb = wc * 16;
    int row0 = blockIdx.x * 64;
    float* red = reinterpret_cast<float*>(smem + RED_OFF);

    float d[2][4] = {};
    float4 pA[4], pB[4];     // two in-flight register sets (chunks ch, ch+1)

    // Prologue: smem[0] <- chunk 0; regs pB <- chunk 1 (LDG issued early)
    ldg_a(x1, row0, 0, tid, pA);
    cpasync_b(smem, 0, tid);
    CP_COMMIT();
    ldg_a(x1, row0, 1, tid, pB);
    sts_a(smem, tid, pA);          // waits only on chunk-0 LDGs (unavoidable once)
    CP_WAIT0();
    __syncthreads();

    // Invariant at top of iter ch: smem[ch&1] ready; set[(ch+1)&1] holds ch+1
    //   (set0 = pA holds even chunks, set1 = pB holds odd chunks)
    for (int ch = 0; ch < 8; ch++) {
        char* nxt = smem + ((ch + 1) & 1) * STAGE_BYTES;
        if (ch < 7) {
            // store chunk ch+1 from regs loaded a FULL iteration ago
            if (ch & 1) sts_a(nxt, tid, pA);
            else        sts_a(nxt, tid, pB);
            cpasync_b(nxt, ch + 1, tid);
            CP_COMMIT();
        }
        if (ch < 6) {
            // refill the just-consumed set with chunk ch+2
            if (ch & 1) ldg_a(x1, row0, ch + 2, tid, pB);
            else        ldg_a(x1, row0, ch + 2, tid, pA);
        }
        compute_chunk(smem_u32(smem + (ch & 1) * STAGE_BYTES), m0, nb, lane, d);
        if (ch < 7) {
            CP_WAIT0();
            __syncthreads();
        }
    }

    // fused epilogue: relu(D + c)*U over this warp's 16 cols, reduce -> out
    int g = lane >> 2, tg2 = (lane & 3) * 2;
    float accA = 0.0f, accB = 0.0f;
#pragma unroll
    for (int j = 0; j < 2; j++) {
        int col = nb + j * 8 + tg2;
        float c0 = g_c[col], c1 = g_c[col + 1];
        float u0 = U[col], u1 = U[col + 1];
        accA += fmaxf(d[j][0] + c0, 0.0f) * u0 + fmaxf(d[j][1] + c1, 0.0f) * u1;
        accB += fmaxf(d[j][2] + c0, 0.0f) * u0 + fmaxf(d[j][3] + c1, 0.0f) * u1;
    }
    accA += __shfl_xor_sync(0xFFFFFFFFu, accA, 1);
    accA += __shfl_xor_sync(0xFFFFFFFFu, accA, 2);
    accB += __shfl_xor_sync(0xFFFFFFFFu, accB, 1);
    accB += __shfl_xor_sync(0xFFFFFFFFu, accB, 2);
    if ((lane & 3) == 0) {
        red[wc * 64 + m0 + g] = accA;
        red[wc * 64 + m0 + 8 + g] = accB;
    }
    __syncthreads();
    if (tid < 64) {
        out[row0 + tid] = (red[tid] + red[64 + tid]) + (red[128 + tid] + red[192 + tid]);
    }
}

// ---------------------------------------------------------------------------
extern "C" void kernel_launch(void* const* d_in, const int* in_sizes, int n_in,
                              void* d_out, int out_size) {
    const float* x1 = (const float*)d_in[0];  // (8192, 1024)
    const float* x2 = (const float*)d_in[1];  // (1, 1024)
    const float* V  = (const float*)d_in[2];  // (64, 2048)
    const float* W  = (const float*)d_in[3];  // (64, 1024, 1024)
    const float* b  = (const float*)d_in[4];  // (64,)
    const float* U  = (const float*)d_in[5];  // (64, 1)
    float* out = (float*)d_out;               // (8192, 1)

    cudaFuncSetAttribute(gemm_mma, cudaFuncAttributeMaxDynamicSharedMemorySize, SMEM_TOTAL);

    wx2_kernel<<<8192 + 64, 256>>>(W, V, x2, b);     // HBM-bound + fused c blocks
    gemm_mma<<<128, 512, SMEM_TOTAL>>>(x1, U, out);  // decoupled-pipeline HMMA GEMM
}